// round 3
// baseline (speedup 1.0000x reference)
#include <cuda_runtime.h>
#include <cuda_bf16.h>

// CompositeLoss fused single-kernel: focal + sparsity + concentration
// over pred/target [16,20,256,256] f32, with moment expansion of the
// concentration term and last-block finalize (self-resetting accumulators).

#define PLANES   320          // B*C = 16*20
#define SEGS     4            // blocks per plane
#define THREADS  256          // 8 warps
#define HW       65536        // 256*256
#define F4_PLANE 16384        // HW/4
#define NTOT_D   20971520.0

// Per-plane moments: [mass, sty, stx, sp, spy, spx, spyy, spxx]
__device__ float        g_plane[PLANES * 8];
// Global sums: [fl(log2-scale), sum x^2, sum x*t, sum |x|]
__device__ double       g_glob[4];
__device__ unsigned int g_count;

__device__ __forceinline__ float frcp(float x) {
    float r; asm("rcp.approx.f32 %0, %1;" : "=f"(r) : "f"(x)); return r;
}

struct G4 { float psum, q1, q2, tsum, tq1; };

// Process 4 elements (one float4 pair). Accumulates core terms, returns
// group moments for j-weighted (within-float4 x offset) sums.
__device__ __forceinline__ void proc4(const float4 pv, const float4 tv,
                                      float& fl, float& sqx, float& sxt, float& ab,
                                      G4& g)
{
    const float xv[4] = {pv.x, pv.y, pv.z, pv.w};
    const float tt[4] = {tv.x, tv.y, tv.z, tv.w};
    float p[4];
    #pragma unroll
    for (int j = 0; j < 4; j++) {
        const float x = xv[j];
        const float t = tt[j];                 // 0.0f or 1.0f
        const float e   = __expf(-x);          // FMUL(imm) + MUFU.EX2
        const float r   = frcp(1.0f + e);      // p = sigmoid(x)
        const float omp = e * r;               // 1-p
        const float pt  = fmaf(t, r - omp, omp);
        const float u   = 1.0f - pt;
        const float a   = fmaf(t, -0.5f, 0.75f);
        const float lg  = __log2f(pt + 1e-8f); // scale by ln2 at the end
        fl  = fmaf(a * u * u, lg, fl);
        sqx = fmaf(x, x, sqx);
        sxt = fmaf(x, t, sxt);
        ab += fabsf(x);
        p[j] = r;
    }
    g.psum = (p[0] + p[1]) + (p[2] + p[3]);
    g.q1   = fmaf(3.0f, p[3], fmaf(2.0f, p[2], p[1]));   // sum p_j * j
    g.q2   = fmaf(9.0f, p[3], fmaf(4.0f, p[2], p[1]));   // sum p_j * j^2
    g.tsum = (tt[0] + tt[1]) + (tt[2] + tt[3]);
    g.tq1  = fmaf(3.0f, tt[3], fmaf(2.0f, tt[2], tt[1]));
}

__global__ __launch_bounds__(THREADS) void composite_kernel(
    const float4* __restrict__ pred, const float4* __restrict__ tgt,
    float* __restrict__ out, int out_size)
{
    const int plane = blockIdx.x >> 2;
    const int seg   = blockIdx.x & 3;
    const int warp  = threadIdx.x >> 5;
    const int lane  = threadIdx.x & 31;

    const float4* pp = pred + plane * F4_PLANE;
    const float4* tp = tgt  + plane * F4_PLANE;

    const int   row0 = seg * 64 + warp * 8;     // 8 rows per warp
    const float x0a  = (float)(lane * 4);       // column group A base x
    const float x0b  = (float)(128 + lane * 4); // column group B base x

    float fl = 0.f, sqx = 0.f, sxt = 0.f, ab = 0.f;
    float Pa = 0.f, Pb = 0.f, Q1a = 0.f, Q2a = 0.f, Q1b = 0.f, Q2b = 0.f;
    float spy = 0.f, spyy = 0.f;
    float Ta = 0.f, Tb = 0.f, TQ1a = 0.f, TQ1b = 0.f, sty = 0.f;

    #pragma unroll 1   // cap MLP_p1: 4 LDG.128 per iteration
    for (int r = 0; r < 8; r++) {
        const int row = row0 + r;
        const int off = row * 64 + lane;
        const float4 pA = pp[off],      tA = tp[off];
        const float4 pB = pp[off + 32], tB = tp[off + 32];

        G4 ga, gb;
        proc4(pA, tA, fl, sqx, sxt, ab, ga);
        proc4(pB, tB, fl, sqx, sxt, ab, gb);

        Pa += ga.psum;  Pb += gb.psum;
        Q1a += ga.q1;   Q2a += ga.q2;
        Q1b += gb.q1;   Q2b += gb.q2;
        Ta += ga.tsum;  Tb += gb.tsum;
        TQ1a += ga.tq1; TQ1b += gb.tq1;

        const float y    = (float)row;
        const float psum = ga.psum + gb.psum;
        const float tsum = ga.tsum + gb.tsum;
        const float m    = psum * y;
        spy  += m;
        spyy  = fmaf(m, y, spyy);
        sty   = fmaf(tsum, y, sty);
    }

    // Per-thread x0 folds (x = x0 + j within each float4)
    const float sp   = Pa + Pb;
    const float spx  = fmaf(x0a, Pa, Q1a) + fmaf(x0b, Pb, Q1b);
    const float spxx = fmaf(x0a, fmaf(x0a, Pa, 2.0f * Q1a), Q2a)
                     + fmaf(x0b, fmaf(x0b, Pb, 2.0f * Q1b), Q2b);
    const float mass = Ta + Tb;
    const float stx  = fmaf(x0a, Ta, TQ1a) + fmaf(x0b, Tb, TQ1b);

    // ---- block reduction of 12 values ----
    float vals[12] = {fl, sqx, sxt, ab, mass, sty, stx, sp, spy, spx, spyy, spxx};
    #pragma unroll
    for (int offm = 16; offm > 0; offm >>= 1) {
        #pragma unroll
        for (int k = 0; k < 12; k++)
            vals[k] += __shfl_down_sync(0xffffffffu, vals[k], offm);
    }
    __shared__ float smem[THREADS / 32][12];
    if (lane == 0) {
        #pragma unroll
        for (int k = 0; k < 12; k++) smem[warp][k] = vals[k];
    }
    __syncthreads();

    __shared__ bool s_last;
    if (threadIdx.x == 0) {
        float rr[12];
        #pragma unroll
        for (int k = 0; k < 12; k++) rr[k] = smem[0][k];
        for (int w = 1; w < THREADS / 32; w++)
            #pragma unroll
            for (int k = 0; k < 12; k++) rr[k] += smem[w][k];

        atomicAdd(&g_glob[0], (double)rr[0]);
        atomicAdd(&g_glob[1], (double)rr[1]);
        atomicAdd(&g_glob[2], (double)rr[2]);
        atomicAdd(&g_glob[3], (double)rr[3]);
        float* P = &g_plane[plane * 8];
        #pragma unroll
        for (int k = 0; k < 8; k++) atomicAdd(&P[k], rr[4 + k]);

        __threadfence();
        const unsigned c = atomicAdd(&g_count, 1u);
        s_last = (c == gridDim.x - 1);
    }
    __syncthreads();
    if (!s_last) return;

    // ---- last block: finalize + reset ----
    __threadfence();
    __shared__ float s_conc, s_mass;
    __shared__ int   s_nv;
    if (threadIdx.x == 0) { s_conc = 0.f; s_mass = 0.f; s_nv = 0; }
    __syncthreads();

    for (int i = threadIdx.x; i < PLANES; i += THREADS) {
        const float* P = &g_plane[i * 8];
        const float m = P[0];
        atomicAdd(&s_mass, m);
        if (m > 0.0f) {
            const float cy = P[1] / m;
            const float cx = P[2] / m;
            const float num = P[6] - 2.0f * cy * P[4] + cy * cy * P[3]
                            + P[7] - 2.0f * cx * P[5] + cx * cx * P[3];
            atomicAdd(&s_conc, num * (1.0f / 65536.0f));
            atomicAdd(&s_nv, 1);
        }
    }
    __syncthreads();

    if (threadIdx.x == 0) {
        const double N = NTOT_D;
        const float focal    = (float)(-0.6931471805599453 * g_glob[0] / N);
        const double sq      = (g_glob[1] - 2.0 * g_glob[2] + (double)s_mass) / N;
        const float sparsity = (float)(sq + g_glob[3] / N);
        const float conc     = (s_nv > 0) ? (s_conc / (float)s_nv) : 0.0f;
        out[0] = focal + 0.8f * sparsity + 1.5f * conc;
        if (out_size >= 4) { out[1] = focal; out[2] = sparsity; out[3] = conc; }
    }
    __syncthreads();

    // reset accumulators for next launch (graph replay)
    for (int i = threadIdx.x; i < PLANES * 8; i += THREADS) g_plane[i] = 0.0f;
    if (threadIdx.x < 4) g_glob[threadIdx.x] = 0.0;
    if (threadIdx.x == 0) g_count = 0u;
}

extern "C" void kernel_launch(void* const* d_in, const int* in_sizes, int n_in,
                              void* d_out, int out_size) {
    const float4* pred = (const float4*)d_in[0];
    const float4* tgt  = (const float4*)d_in[1];
    composite_kernel<<<PLANES * SEGS, THREADS>>>(pred, tgt, (float*)d_out, out_size);
}